// round 1
// baseline (speedup 1.0000x reference)
#include <cuda_runtime.h>

#define NB 32768
#define NT 64
#define NIN 4
#define NH 64
#define NM 4
#define NHB 256

// inter-kernel scratch for selected expert index (no allocations allowed)
__device__ int g_idx[NB];

__device__ __forceinline__ float sigf(float x) {
    float e = __expf(-x);
    return __fdividef(1.f, 1.f + e);
}
__device__ __forceinline__ float tanhfast(float x) {
    float e = __expf(-2.f * x);
    return __fdividef(2.f, 1.f + e) - 1.f;
}

struct SmemGRU {
    float Whh[192][68];   // padded stride 68 -> conflict-free LDS.128 across lanes
    float Wih[192][4];
    float Br[64], Bz[64], Bin[64], Bhn[64];
    float Whd[4][64];
    float bhd[4];
    float H[8][8][64];    // [warp][sample][hidden]
};

// One warp handles 8 samples; block = 8 warps = 64 samples; grid = 512.
// Lane owns hidden units u0=lane, u1=lane+32 (rows u, u+64, u+128 of the 192 gate rows).
__global__ void __launch_bounds__(256) gru_sel_kernel(
    const float* __restrict__ Hn,
    const float* __restrict__ gum,
    const float* __restrict__ Wih,
    const float* __restrict__ Whh,
    const float* __restrict__ bih,
    const float* __restrict__ bhh,
    const float* __restrict__ Whead,
    const float* __restrict__ bhead,
    float* __restrict__ out)
{
    extern __shared__ char smem_raw[];
    SmemGRU& S = *reinterpret_cast<SmemGRU*>(smem_raw);
    const int tid = threadIdx.x;

    for (int i = tid; i < 192 * 64; i += 256) S.Whh[i >> 6][i & 63] = Whh[i];
    for (int i = tid; i < 192 * 4;  i += 256) S.Wih[i >> 2][i & 3]  = Wih[i];
    if (tid < 64) {
        S.Br[tid]  = bih[tid]        + bhh[tid];
        S.Bz[tid]  = bih[64 + tid]   + bhh[64 + tid];
        S.Bin[tid] = bih[128 + tid];
        S.Bhn[tid] = bhh[128 + tid];
    }
    if (tid < 256) S.Whd[tid >> 6][tid & 63] = Whead[tid];
    if (tid < 4)   S.bhd[tid] = bhead[tid];

    const int w = tid >> 5, lane = tid & 31;
#pragma unroll
    for (int s = 0; s < 8; s++) { S.H[w][s][lane] = 0.f; S.H[w][s][lane + 32] = 0.f; }
    __syncthreads();

    const int gw = blockIdx.x * 8 + w;
    const int b0 = gw * 8;
    const float* hp = Hn + (size_t)b0 * NT * NIN;
    const int u0 = lane, u1 = lane + 32;

    float ar0[8], az0[8], ain0[8], ahn0[8];
    float ar1[8], az1[8], ain1[8], ahn1[8];

#pragma unroll 1
    for (int t = 0; t < NT; t++) {
        // per-step input contribution (W_ih is tiny: dot-4)
        const float4 wr0i = *(const float4*)S.Wih[u0];
        const float4 wz0i = *(const float4*)S.Wih[u0 + 64];
        const float4 wn0i = *(const float4*)S.Wih[u0 + 128];
        const float4 wr1i = *(const float4*)S.Wih[u1];
        const float4 wz1i = *(const float4*)S.Wih[u1 + 64];
        const float4 wn1i = *(const float4*)S.Wih[u1 + 128];
        const float br0 = S.Br[u0], bz0 = S.Bz[u0], bi0 = S.Bin[u0], bh0 = S.Bhn[u0];
        const float br1 = S.Br[u1], bz1 = S.Bz[u1], bi1 = S.Bin[u1], bh1 = S.Bhn[u1];
#pragma unroll
        for (int s = 0; s < 8; s++) {
            const float4 x = __ldg((const float4*)(hp + ((size_t)s * NT + t) * NIN));
            ar0[s]  = br0 + wr0i.x * x.x + wr0i.y * x.y + wr0i.z * x.z + wr0i.w * x.w;
            az0[s]  = bz0 + wz0i.x * x.x + wz0i.y * x.y + wz0i.z * x.z + wz0i.w * x.w;
            ain0[s] = bi0 + wn0i.x * x.x + wn0i.y * x.y + wn0i.z * x.z + wn0i.w * x.w;
            ahn0[s] = bh0;
            ar1[s]  = br1 + wr1i.x * x.x + wr1i.y * x.y + wr1i.z * x.z + wr1i.w * x.w;
            az1[s]  = bz1 + wz1i.x * x.x + wz1i.y * x.y + wz1i.z * x.z + wz1i.w * x.w;
            ain1[s] = bi1 + wn1i.x * x.x + wn1i.y * x.y + wn1i.z * x.z + wn1i.w * x.w;
            ahn1[s] = bh1;
        }
        // recurrence: 6 gate rows x 64-dot x 8 samples; weight quads reused across samples
#pragma unroll 2
        for (int kc = 0; kc < NH; kc += 4) {
            const float4 wr0 = *(const float4*)&S.Whh[u0][kc];
            const float4 wz0 = *(const float4*)&S.Whh[u0 + 64][kc];
            const float4 wn0 = *(const float4*)&S.Whh[u0 + 128][kc];
            const float4 wr1 = *(const float4*)&S.Whh[u1][kc];
            const float4 wz1 = *(const float4*)&S.Whh[u1 + 64][kc];
            const float4 wn1 = *(const float4*)&S.Whh[u1 + 128][kc];
#pragma unroll
            for (int s = 0; s < 8; s++) {
                const float4 h4 = *(const float4*)&S.H[w][s][kc];   // broadcast read
                ar0[s]  += wr0.x * h4.x + wr0.y * h4.y + wr0.z * h4.z + wr0.w * h4.w;
                az0[s]  += wz0.x * h4.x + wz0.y * h4.y + wz0.z * h4.z + wz0.w * h4.w;
                ahn0[s] += wn0.x * h4.x + wn0.y * h4.y + wn0.z * h4.z + wn0.w * h4.w;
                ar1[s]  += wr1.x * h4.x + wr1.y * h4.y + wr1.z * h4.z + wr1.w * h4.w;
                az1[s]  += wz1.x * h4.x + wz1.y * h4.y + wz1.z * h4.z + wz1.w * h4.w;
                ahn1[s] += wn1.x * h4.x + wn1.y * h4.y + wn1.z * h4.z + wn1.w * h4.w;
            }
        }
        __syncwarp();   // all lanes done reading H before anyone overwrites
#pragma unroll
        for (int s = 0; s < 8; s++) {
            const float ho0 = S.H[w][s][u0];
            const float ho1 = S.H[w][s][u1];
            const float r0 = sigf(ar0[s]), z0 = sigf(az0[s]);
            const float n0 = tanhfast(ain0[s] + r0 * ahn0[s]);
            const float r1 = sigf(ar1[s]), z1 = sigf(az1[s]);
            const float n1 = tanhfast(ain1[s] + r1 * ahn1[s]);
            S.H[w][s][u0] = (1.f - z0) * n0 + z0 * ho0;
            S.H[w][s][u1] = (1.f - z1) * n1 + z1 * ho1;
        }
        __syncwarp();   // new h visible before next step's reads
    }

    // head + gumbel argmax: lane -> (sample = lane>>2, mode = lane&3)
    const int sl = lane >> 2, ml = lane & 3;
    float acc = S.bhd[ml];
#pragma unroll
    for (int kc = 0; kc < NH; kc += 4) {
        const float4 wv = *(const float4*)&S.Whd[ml][kc];
        const float4 h4 = *(const float4*)&S.H[w][sl][kc];
        acc += wv.x * h4.x + wv.y * h4.y + wv.z * h4.z + wv.w * h4.w;
    }
    const int b = b0 + sl;
    const float lv = acc + __ldg(&gum[b * 4 + ml]);
    float best = lv;
    int   bi   = ml;
#pragma unroll
    for (int d = 1; d < 4; d <<= 1) {
        const float ob = __shfl_xor_sync(0xffffffffu, best, d);
        const int   oi = __shfl_xor_sync(0xffffffffu, bi, d);
        if (ob > best || (ob == best && oi < bi)) { best = ob; bi = oi; }   // first-max tiebreak
    }
    out[131072 + b * 4 + ml] = acc;                       // logits
    out[262144 + b * 4 + ml] = (ml == bi) ? 1.f : 0.f;    // onehot (== y_hard in fwd)
    if (ml == 0) { out[393216 + b] = (float)bi; g_idx[b] = bi; }
}

// Expert bank: all 4 experts resident in SMEM, warp per sample (8 samples/warp loop).
__global__ void __launch_bounds__(256) bank_kernel(
    const float* __restrict__ Xp,
    const float* __restrict__ dtp,
    const float* __restrict__ W1,
    const float* __restrict__ b1,
    const float* __restrict__ W2,
    const float* __restrict__ b2,
    float* __restrict__ out)
{
    __shared__ float sW1[4 * 5 * 256];
    __shared__ float sb1[4 * 256];
    __shared__ float sW2[4][256][5];   // padded stride 5 -> conflict-free
    __shared__ float sb2[16];
    const int tid = threadIdx.x;
    for (int i = tid; i < 5120; i += 256) sW1[i] = W1[i];
    for (int i = tid; i < 1024; i += 256) sb1[i] = b1[i];
    for (int i = tid; i < 4096; i += 256) sW2[i >> 10][(i >> 2) & 255][i & 3] = W2[i];
    if (tid < 16) sb2[tid] = b2[tid];
    __syncthreads();

    const float dt = __ldg(dtp);
    const int gw = blockIdx.x * 8 + (tid >> 5);
    const int lane = tid & 31;
#pragma unroll 1
    for (int it = 0; it < 8; it++) {
        const int b = gw * 8 + it;
        const int e = g_idx[b];
        const float4 xv = __ldg((const float4*)(Xp + b * 4));
        const float* w1e = sW1 + e * 1280;
        float hid[8];
#pragma unroll
        for (int j = 0; j < 8; j++) {
            const int u = lane + 32 * j;
            float a = sb1[e * 256 + u]
                    + xv.x * w1e[0 * 256 + u]
                    + xv.y * w1e[1 * 256 + u]
                    + xv.z * w1e[2 * 256 + u]
                    + xv.w * w1e[3 * 256 + u]
                    + dt   * w1e[4 * 256 + u];
            hid[j] = tanhfast(a);
        }
        float f0 = 0.f, f1 = 0.f, f2 = 0.f, f3 = 0.f;
#pragma unroll
        for (int j = 0; j < 8; j++) {
            const int u = lane + 32 * j;
            f0 += hid[j] * sW2[e][u][0];
            f1 += hid[j] * sW2[e][u][1];
            f2 += hid[j] * sW2[e][u][2];
            f3 += hid[j] * sW2[e][u][3];
        }
#pragma unroll
        for (int off = 16; off >= 1; off >>= 1) {
            f0 += __shfl_xor_sync(0xffffffffu, f0, off);
            f1 += __shfl_xor_sync(0xffffffffu, f1, off);
            f2 += __shfl_xor_sync(0xffffffffu, f2, off);
            f3 += __shfl_xor_sync(0xffffffffu, f3, off);
        }
        if (lane < 4) {
            float fv = (lane == 0) ? f0 : (lane == 1) ? f1 : (lane == 2) ? f2 : f3;
            fv += sb2[e * 4 + lane];
            out[b * 4 + lane] = __ldg(&Xp[b * 4 + lane]) + dt * fv;   // pred
        }
    }
}

extern "C" void kernel_launch(void* const* d_in, const int* in_sizes, int n_in,
                              void* d_out, int out_size) {
    const float* Hn    = (const float*)d_in[0];
    const float* Xp    = (const float*)d_in[1];
    const float* dtp   = (const float*)d_in[2];
    const float* gum   = (const float*)d_in[3];
    const float* Wih   = (const float*)d_in[4];
    const float* Whh   = (const float*)d_in[5];
    const float* bih   = (const float*)d_in[6];
    const float* bhh   = (const float*)d_in[7];
    const float* Whead = (const float*)d_in[8];
    const float* bhead = (const float*)d_in[9];
    const float* W1    = (const float*)d_in[10];
    const float* b1    = (const float*)d_in[11];
    const float* W2    = (const float*)d_in[12];
    const float* b2    = (const float*)d_in[13];
    float* out = (float*)d_out;

    const int smem = (int)sizeof(SmemGRU);   // ~73.7 KB -> needs opt-in (idempotent, non-stream call)
    cudaFuncSetAttribute(gru_sel_kernel, cudaFuncAttributeMaxDynamicSharedMemorySize, smem);

    gru_sel_kernel<<<512, 256, smem>>>(Hn, gum, Wih, Whh, bih, bhh, Whead, bhead, out);
    bank_kernel<<<512, 256>>>(Xp, dtp, W1, b1, W2, b2, out);
}

// round 3
// speedup vs baseline: 1.2954x; 1.2954x over previous
#include <cuda_runtime.h>
#include <cstdint>

#define NB 32768
#define NT 64
#define NIN 4
#define NH 64

__device__ int g_idx[NB];

typedef unsigned long long u64;

__device__ __forceinline__ float sigf(float x) {
    float e = __expf(-x);
    return __fdividef(1.f, 1.f + e);
}
__device__ __forceinline__ float tanhfast(float x) {
    float e = __expf(-2.f * x);
    return __fdividef(2.f, 1.f + e) - 1.f;
}

// ---- f32x2 packed helpers (sm_100+); .b64 regs via "l" constraint ----
__device__ __forceinline__ u64 splat2(float w) {
    u64 d; asm("mov.b64 %0, {%1, %1};" : "=l"(d) : "f"(w)); return d;
}
__device__ __forceinline__ u64 pk2(float a, float b) {
    u64 d; asm("mov.b64 %0, {%1, %2};" : "=l"(d) : "f"(a), "f"(b)); return d;
}
__device__ __forceinline__ void upk2(u64 d, float& a, float& b) {
    asm("mov.b64 {%0, %1}, %2;" : "=f"(a), "=f"(b) : "l"(d));
}
__device__ __forceinline__ void fma2(u64& acc, u64 a, u64 b) {
    asm("fma.rn.f32x2 %0, %1, %2, %3;" : "=l"(acc) : "l"(a), "l"(b), "l"(acc));
}
__device__ __forceinline__ void lds_2x64(uint32_t addr, u64& a, u64& b) {
    asm volatile("ld.shared.v2.b64 {%0, %1}, [%2];" : "=l"(a), "=l"(b) : "r"(addr));
}
__device__ __forceinline__ u64 lds_64(uint32_t addr) {
    u64 d; asm volatile("ld.shared.b64 %0, [%1];" : "=l"(d) : "r"(addr)); return d;
}
__device__ __forceinline__ void sts_64(uint32_t addr, u64 v) {
    asm volatile("st.shared.b64 [%0], %1;" :: "r"(addr), "l"(v) : "memory");
}

struct SmemGRU {
    float Whh[192][68];   // 272B row stride: 17×16B -> conflict-free LDS.128
    float Wih[192][4];
    float Br[64], Bz[64], Bin[64], Bhn[64];
    float Whd[4][64];
    float bhd[4];
    float H[4][64][12];   // [warp][k][8 samples + pad4]; 48B rows -> 16B-aligned v2.b64
};

// 128 threads = 4 warps; warp = 8 samples (4 f32x2 pairs); grid = 1024.
__global__ void __launch_bounds__(128) gru_sel_kernel(
    const float* __restrict__ Hn,
    const float* __restrict__ gum,
    const float* __restrict__ Wih,
    const float* __restrict__ Whh,
    const float* __restrict__ bih,
    const float* __restrict__ bhh,
    const float* __restrict__ Whead,
    const float* __restrict__ bhead,
    float* __restrict__ out)
{
    extern __shared__ char smem_raw[];
    SmemGRU& S = *reinterpret_cast<SmemGRU*>(smem_raw);
    const int tid = threadIdx.x;

    for (int i = tid; i < 192 * 64; i += 128) S.Whh[i >> 6][i & 63] = Whh[i];
    for (int i = tid; i < 192 * 4;  i += 128) S.Wih[i >> 2][i & 3]  = Wih[i];
    if (tid < 64) {
        S.Br[tid]  = bih[tid]        + bhh[tid];
        S.Bz[tid]  = bih[64 + tid]   + bhh[64 + tid];
        S.Bin[tid] = bih[128 + tid];
        S.Bhn[tid] = bhh[128 + tid];
    }
    for (int i = tid; i < 256; i += 128) S.Whd[i >> 6][i & 63] = Whead[i];
    if (tid < 4) S.bhd[tid] = bhead[tid];
    for (int i = tid; i < 4 * 64 * 12; i += 128) ((float*)S.H)[i] = 0.f;
    __syncthreads();

    const int w = tid >> 5, lane = tid & 31;
    const int u0 = lane, u1 = lane + 32;
    const int b0 = (blockIdx.x * 4 + w) * 8;
    const float* hp = Hn + (size_t)b0 * NT * NIN;

    const uint32_t Hb = (uint32_t)__cvta_generic_to_shared(&S.H[w][0][0]);
    const uint32_t Hu0 = Hb + u0 * 48, Hu1 = Hb + u1 * 48;

    // loop-invariant bias splats
    const u64 br0 = splat2(S.Br[u0]),  br1 = splat2(S.Br[u1]);
    const u64 bz0 = splat2(S.Bz[u0]),  bz1 = splat2(S.Bz[u1]);
    const u64 bi0 = splat2(S.Bin[u0]), bi1 = splat2(S.Bin[u1]);
    const u64 bh0 = splat2(S.Bhn[u0]), bh1 = splat2(S.Bhn[u1]);
    // input weights (tiny, keep in regs across t)
    const float4 wiR0 = *(const float4*)S.Wih[u0];
    const float4 wiZ0 = *(const float4*)S.Wih[u0 + 64];
    const float4 wiN0 = *(const float4*)S.Wih[u0 + 128];
    const float4 wiR1 = *(const float4*)S.Wih[u1];
    const float4 wiZ1 = *(const float4*)S.Wih[u1 + 64];
    const float4 wiN1 = *(const float4*)S.Wih[u1 + 128];

    u64 ar[2][4], az[2][4], ahn[2][4], ain[2][4];

#pragma unroll 1
    for (int t = 0; t < NT; t++) {
        // ---- input phase: pack x into sample-pair lanes ----
        u64 xp[4][4];   // [k][sp]
#pragma unroll
        for (int sp = 0; sp < 4; sp++) {
            const float4 xa = __ldg((const float4*)(hp + ((size_t)(2 * sp)     * NT + t) * NIN));
            const float4 xb = __ldg((const float4*)(hp + ((size_t)(2 * sp + 1) * NT + t) * NIN));
            xp[0][sp] = pk2(xa.x, xb.x);
            xp[1][sp] = pk2(xa.y, xb.y);
            xp[2][sp] = pk2(xa.z, xb.z);
            xp[3][sp] = pk2(xa.w, xb.w);
        }
#define IROW(W4, ACC, BIAS)                                              \
        {   const u64 s0 = splat2((W4).x), s1 = splat2((W4).y),           \
                      s2 = splat2((W4).z), s3 = splat2((W4).w);           \
            _Pragma("unroll")                                             \
            for (int sp = 0; sp < 4; sp++) {                              \
                ACC[sp] = BIAS;                                           \
                fma2(ACC[sp], s0, xp[0][sp]);                             \
                fma2(ACC[sp], s1, xp[1][sp]);                             \
                fma2(ACC[sp], s2, xp[2][sp]);                             \
                fma2(ACC[sp], s3, xp[3][sp]);                             \
            } }
        IROW(wiR0, ar[0], br0)  IROW(wiZ0, az[0], bz0)  IROW(wiN0, ain[0], bi0)
        IROW(wiR1, ar[1], br1)  IROW(wiZ1, az[1], bz1)  IROW(wiN1, ain[1], bi1)
#pragma unroll
        for (int sp = 0; sp < 4; sp++) { ahn[0][sp] = bh0; ahn[1][sp] = bh1; }

        // ---- recurrence: 6 gate rows x 64-dot, f32x2 over sample pairs ----
#pragma unroll 4
        for (int kc = 0; kc < NH; kc += 4) {
            u64 hk[4][4];   // [k][sp], broadcast loads
#pragma unroll
            for (int k = 0; k < 4; k++) {
                const uint32_t a = Hb + (kc + k) * 48;
                lds_2x64(a,      hk[k][0], hk[k][1]);
                lds_2x64(a + 16, hk[k][2], hk[k][3]);
            }
#define RROW(ROW, ACC)                                                    \
            {   const float4 w4 = *(const float4*)&S.Whh[ROW][kc];        \
                const u64 s0 = splat2(w4.x), s1 = splat2(w4.y),           \
                          s2 = splat2(w4.z), s3 = splat2(w4.w);           \
                _Pragma("unroll")                                         \
                for (int sp = 0; sp < 4; sp++) {                          \
                    fma2(ACC[sp], s0, hk[0][sp]);                         \
                    fma2(ACC[sp], s1, hk[1][sp]);                         \
                    fma2(ACC[sp], s2, hk[2][sp]);                         \
                    fma2(ACC[sp], s3, hk[3][sp]);                         \
                } }
            RROW(u0,       ar[0])
            RROW(u0 + 64,  az[0])
            RROW(u0 + 128, ahn[0])
            RROW(u1,       ar[1])
            RROW(u1 + 64,  az[1])
            RROW(u1 + 128, ahn[1])
        }
        __syncwarp();   // all lanes finished reading old H

        // ---- activations (scalar, MUFU pipe) ----
#pragma unroll
        for (int un = 0; un < 2; un++) {
            const uint32_t Hu = un ? Hu1 : Hu0;
#pragma unroll
            for (int sp = 0; sp < 4; sp++) {
                float a0, a1, z0f, z1f, i0, i1, n0h, n1h;
                upk2(ar[un][sp],  a0,  a1);
                upk2(az[un][sp],  z0f, z1f);
                upk2(ain[un][sp], i0,  i1);
                upk2(ahn[un][sp], n0h, n1h);
                float ho0, ho1;
                upk2(lds_64(Hu + sp * 8), ho0, ho1);
                const float r0 = sigf(a0), r1 = sigf(a1);
                const float zz0 = sigf(z0f), zz1 = sigf(z1f);
                const float n0 = tanhfast(i0 + r0 * n0h);
                const float n1 = tanhfast(i1 + r1 * n1h);
                const float h0 = n0 + zz0 * (ho0 - n0);
                const float h1 = n1 + zz1 * (ho1 - n1);
                sts_64(Hu + sp * 8, pk2(h0, h1));
            }
        }
        __syncwarp();   // new h visible to all lanes
    }

    // ---- head + gumbel argmax: lane -> (sample = lane>>2, mode = lane&3) ----
    const int sl = lane >> 2, ml = lane & 3;
    float acc = S.bhd[ml];
#pragma unroll
    for (int k = 0; k < NH; k++)
        acc += S.Whd[ml][k] * S.H[w][k][sl];
    const int b = b0 + sl;
    const float lv = acc + __ldg(&gum[b * 4 + ml]);
    float best = lv;
    int   bi   = ml;
#pragma unroll
    for (int d = 1; d < 4; d <<= 1) {
        const float ob = __shfl_xor_sync(0xffffffffu, best, d);
        const int   oi = __shfl_xor_sync(0xffffffffu, bi, d);
        if (ob > best || (ob == best && oi < bi)) { best = ob; bi = oi; }
    }
    out[131072 + b * 4 + ml] = acc;                       // logits
    out[262144 + b * 4 + ml] = (ml == bi) ? 1.f : 0.f;    // onehot
    if (ml == 0) { out[393216 + b] = (float)bi; g_idx[b] = bi; }
}

// Expert bank: unchanged (35us, not the bottleneck).
__global__ void __launch_bounds__(256) bank_kernel(
    const float* __restrict__ Xp,
    const float* __restrict__ dtp,
    const float* __restrict__ W1,
    const float* __restrict__ b1,
    const float* __restrict__ W2,
    const float* __restrict__ b2,
    float* __restrict__ out)
{
    __shared__ float sW1[4 * 5 * 256];
    __shared__ float sb1[4 * 256];
    __shared__ float sW2[4][256][5];
    __shared__ float sb2[16];
    const int tid = threadIdx.x;
    for (int i = tid; i < 5120; i += 256) sW1[i] = W1[i];
    for (int i = tid; i < 1024; i += 256) sb1[i] = b1[i];
    for (int i = tid; i < 4096; i += 256) sW2[i >> 10][(i >> 2) & 255][i & 3] = W2[i];
    if (tid < 16) sb2[tid] = b2[tid];
    __syncthreads();

    const float dt = __ldg(dtp);
    const int gw = blockIdx.x * 8 + (tid >> 5);
    const int lane = tid & 31;
#pragma unroll 1
    for (int it = 0; it < 8; it++) {
        const int b = gw * 8 + it;
        const int e = g_idx[b];
        const float4 xv = __ldg((const float4*)(Xp + b * 4));
        const float* w1e = sW1 + e * 1280;
        float hid[8];
#pragma unroll
        for (int j = 0; j < 8; j++) {
            const int u = lane + 32 * j;
            float a = sb1[e * 256 + u]
                    + xv.x * w1e[0 * 256 + u]
                    + xv.y * w1e[1 * 256 + u]
                    + xv.z * w1e[2 * 256 + u]
                    + xv.w * w1e[3 * 256 + u]
                    + dt   * w1e[4 * 256 + u];
            hid[j] = tanhfast(a);
        }
        float f0 = 0.f, f1 = 0.f, f2 = 0.f, f3 = 0.f;
#pragma unroll
        for (int j = 0; j < 8; j++) {
            const int u = lane + 32 * j;
            f0 += hid[j] * sW2[e][u][0];
            f1 += hid[j] * sW2[e][u][1];
            f2 += hid[j] * sW2[e][u][2];
            f3 += hid[j] * sW2[e][u][3];
        }
#pragma unroll
        for (int off = 16; off >= 1; off >>= 1) {
            f0 += __shfl_xor_sync(0xffffffffu, f0, off);
            f1 += __shfl_xor_sync(0xffffffffu, f1, off);
            f2 += __shfl_xor_sync(0xffffffffu, f2, off);
            f3 += __shfl_xor_sync(0xffffffffu, f3, off);
        }
        if (lane < 4) {
            float fv = (lane == 0) ? f0 : (lane == 1) ? f1 : (lane == 2) ? f2 : f3;
            fv += sb2[e * 4 + lane];
            out[b * 4 + lane] = __ldg(&Xp[b * 4 + lane]) + dt * fv;
        }
    }
}

extern "C" void kernel_launch(void* const* d_in, const int* in_sizes, int n_in,
                              void* d_out, int out_size) {
    const float* Hn    = (const float*)d_in[0];
    const float* Xp    = (const float*)d_in[1];
    const float* dtp   = (const float*)d_in[2];
    const float* gum   = (const float*)d_in[3];
    const float* Wih   = (const float*)d_in[4];
    const float* Whh   = (const float*)d_in[5];
    const float* bih   = (const float*)d_in[6];
    const float* bhh   = (const float*)d_in[7];
    const float* Whead = (const float*)d_in[8];
    const float* bhead = (const float*)d_in[9];
    const float* W1    = (const float*)d_in[10];
    const float* b1    = (const float*)d_in[11];
    const float* W2    = (const float*)d_in[12];
    const float* b2    = (const float*)d_in[13];
    float* out = (float*)d_out;

    const int smem = (int)sizeof(SmemGRU);
    cudaFuncSetAttribute(gru_sel_kernel, cudaFuncAttributeMaxDynamicSharedMemorySize, smem);

    gru_sel_kernel<<<1024, 128, smem>>>(Hn, gum, Wih, Whh, bih, bhh, Whead, bhead, out);
    bank_kernel<<<512, 256>>>(Xp, dtp, W1, b1, W2, b2, out);
}